// round 1
// baseline (speedup 1.0000x reference)
#include <cuda_runtime.h>
#include <cfloat>

// Problem constants (PointPairNet: B=4, N=512, D=3)
#define B_   4
#define N_   512
#define D_   3
#define C1   64    // hidden width after layer 1/2
#define C3   128   // layer-3 output channels
#define TI   16
#define TJ   16
#define PAIRS (TI*TJ)   // 256 pairs per block

typedef unsigned long long ull;

// ---------- device-global scratch (no allocations allowed) ----------
__device__ float    g_U[B_*N_*C1];     // Ai contribution + b1
__device__ float    g_V[B_*N_*C1];     // Aj contribution
__device__ unsigned g_Penc[B_*C3];     // order-encoded per-channel max

// ---------- helpers ----------
__device__ __forceinline__ ull fma2(ull a, ull b, ull c) {
    ull d;
    asm("fma.rn.f32x2 %0, %1, %2, %3;" : "=l"(d) : "l"(a), "l"(b), "l"(c));
    return d;
}
__device__ __forceinline__ float hsum2(ull a) {
    float lo, hi;
    asm("mov.b64 {%0, %1}, %2;" : "=f"(lo), "=f"(hi) : "l"(a));
    return lo + hi;
}
// monotone float->uint encoding so unsigned atomicMax == float max
__device__ __forceinline__ unsigned encf(float f) {
    unsigned u = __float_as_uint(f);
    return (u & 0x80000000u) ? ~u : (u | 0x80000000u);
}
__device__ __forceinline__ float decf(unsigned e) {
    return __uint_as_float((e & 0x80000000u) ? (e & 0x7FFFFFFFu) : ~e);
}

// ---------- kernel 0: reset the max accumulators ----------
__global__ void init_kernel() {
    int t = threadIdx.x;
    if (t < B_*C3) g_Penc[t] = 0u;   // 0 < encoding of every finite float
}

// ---------- kernel 1: split first linear layer ----------
// V[row,c] = X[row,:] . W1[c, 0:3]        (point-j contribution)
// U[row,c] = X[row,:] . W1[c, 3:6] + b1[c] (point-i contribution, bias folded)
__global__ void prep_kernel(const float* __restrict__ X,
                            const float* __restrict__ W1,
                            const float* __restrict__ b1) {
    int row = blockIdx.x;          // 0 .. B*N-1
    int c   = threadIdx.x;         // 0 .. 63
    const float* x = X + row * D_;
    float x0 = x[0], x1 = x[1], x2 = x[2];
    const float* w = W1 + c * (2*D_);
    g_V[row*C1 + c] = x0*w[0] + x1*w[1] + x2*w[2];
    g_U[row*C1 + c] = x0*w[3] + x1*w[4] + x2*w[5] + b1[c];
}

// ---------- kernel 2: the heavy per-pair MLP + max-pool ----------
extern __shared__ float smem[];

__global__ void __launch_bounds__(256, 1)
main_kernel(const float* __restrict__ W2, const float* __restrict__ b2,
            const float* __restrict__ W3, const float* __restrict__ b3) {
    float* sH  = smem;                      // [256][64]
    float* sH2 = sH  + PAIRS*C1;            // [256][64]
    float* sU  = sH2 + PAIRS*C1;            // [16][64]
    float* sV  = sU  + TI*C1;               // [16][64]

    const int tid = threadIdx.x;
    const int b   = blockIdx.z;
    const int i0  = blockIdx.x * TI;
    const int j0  = blockIdx.y * TJ;

    // ---- load U/V tiles (coalesced) ----
    const float* Ub = g_U + (b*N_ + i0) * C1;
    const float* Vb = g_V + (b*N_ + j0) * C1;
    #pragma unroll
    for (int t = 0; t < TI*C1; t += 256) {
        sU[t + tid] = Ub[t + tid];
        sV[t + tid] = Vb[t + tid];
    }
    __syncthreads();

    // ---- phase 1: H[p][c] = relu(U[i(p)][c] + V[j(p)][c]) ----
    {
        const int c2 = tid & 31;    // float2 channel index
        const int g  = tid >> 5;    // 8 pair-groups of 32
        #pragma unroll
        for (int pp = 0; pp < 32; ++pp) {
            const int p  = g*32 + pp;
            const int il = p >> 4, jl = p & 15;
            float2 u = *(const float2*)(sU + il*C1 + 2*c2);
            float2 v = *(const float2*)(sV + jl*C1 + 2*c2);
            float2 h;
            h.x = fmaxf(u.x + v.x, 0.f);
            h.y = fmaxf(u.y + v.y, 0.f);
            *(float2*)(sH + p*C1 + 2*c2) = h;   // lanes -> consecutive float2: conflict-free
        }
    }
    __syncthreads();

    // ---- phase 2: H2[p][d] = relu(W2[d,:] . H[p,:] + b2[d]) ----
    // thread = (d = tid%64, pair-group = tid/64); W2 row in registers;
    // H rows read as broadcast LDS.128 (all lanes in a warp share p).
    {
        const int d  = tid & 63;
        const int pg = tid >> 6;    // 0..3, 64 pairs each
        ull w[32];
        const ulonglong2* wp = (const ulonglong2*)(W2 + d*C1);
        #pragma unroll
        for (int k = 0; k < 16; ++k) { ulonglong2 q = wp[k]; w[2*k] = q.x; w[2*k+1] = q.y; }
        const float bias = b2[d];

        for (int pp = 0; pp < 64; ++pp) {
            const int p = pg*64 + pp;
            const ulonglong2* hp = (const ulonglong2*)(sH + p*C1);
            ull hr[32];
            #pragma unroll
            for (int k = 0; k < 16; ++k) { ulonglong2 q = hp[k]; hr[2*k] = q.x; hr[2*k+1] = q.y; }
            ull a0 = 0ull, a1 = 0ull;
            #pragma unroll
            for (int k = 0; k < 32; k += 2) {
                a0 = fma2(w[k],   hr[k],   a0);
                a1 = fma2(w[k+1], hr[k+1], a1);
            }
            float s = hsum2(a0) + hsum2(a1) + bias;
            sH2[p*C1 + d] = fmaxf(s, 0.f);      // lanes -> consecutive floats: conflict-free
        }
    }
    __syncthreads();

    // ---- phase 3: H3[p][d] = W3[d,:] . H2[p,:] + b3[d]; running max over pairs ----
    {
        const int d  = tid & 127;
        const int pg = tid >> 7;    // 0..1, 128 pairs each
        ull w[32];
        const ulonglong2* wp = (const ulonglong2*)(W3 + d*C1);
        #pragma unroll
        for (int k = 0; k < 16; ++k) { ulonglong2 q = wp[k]; w[2*k] = q.x; w[2*k+1] = q.y; }
        const float bias = b3[d];
        float lmax = -FLT_MAX;

        for (int pp = 0; pp < 128; ++pp) {
            const int p = pg*128 + pp;
            const ulonglong2* hp = (const ulonglong2*)(sH2 + p*C1);
            ull hr[32];
            #pragma unroll
            for (int k = 0; k < 16; ++k) { ulonglong2 q = hp[k]; hr[2*k] = q.x; hr[2*k+1] = q.y; }
            ull a0 = 0ull, a1 = 0ull;
            #pragma unroll
            for (int k = 0; k < 32; k += 2) {
                a0 = fma2(w[k],   hr[k],   a0);
                a1 = fma2(w[k+1], hr[k+1], a1);
            }
            float v = hsum2(a0) + hsum2(a1) + bias;
            lmax = fmaxf(lmax, v);
        }
        atomicMax(&g_Penc[b*C3 + d], encf(lmax));
    }
}

// ---------- kernel 3: tiny MLP head ----------
__global__ void head_kernel(const float* __restrict__ F1, const float* __restrict__ bf1,
                            const float* __restrict__ F2, const float* __restrict__ bf2,
                            float* __restrict__ out) {
    __shared__ float P[B_*C3];
    __shared__ float Z[B_*64];
    const int tid = threadIdx.x;   // 256
    for (int t = tid; t < B_*C3; t += 256) P[t] = decf(g_Penc[t]);
    __syncthreads();
    {
        const int b = tid >> 6, e = tid & 63;   // 4*64 = 256 threads
        float acc = bf1[e];
        #pragma unroll 4
        for (int dd = 0; dd < C3; ++dd) acc += P[b*C3 + dd] * F1[e*C3 + dd];
        Z[b*64 + e] = fmaxf(acc, 0.f);
    }
    __syncthreads();
    if (tid < B_*2) {
        const int b = tid >> 1, o = tid & 1;
        float acc = bf2[o];
        #pragma unroll 4
        for (int e = 0; e < 64; ++e) acc += Z[b*64 + e] * F2[o*64 + e];
        out[b*2 + o] = acc;
    }
}

// ---------- launch ----------
extern "C" void kernel_launch(void* const* d_in, const int* in_sizes, int n_in,
                              void* d_out, int out_size) {
    const float* X   = (const float*)d_in[0];
    const float* W1  = (const float*)d_in[1];
    const float* b1  = (const float*)d_in[2];
    const float* W2  = (const float*)d_in[3];
    const float* b2  = (const float*)d_in[4];
    const float* W3  = (const float*)d_in[5];
    const float* b3  = (const float*)d_in[6];
    const float* F1  = (const float*)d_in[7];
    const float* bf1 = (const float*)d_in[8];
    const float* F2  = (const float*)d_in[9];
    const float* bf2 = (const float*)d_in[10];

    const size_t shmem = (size_t)(PAIRS*C1 + PAIRS*C1 + TI*C1 + TJ*C1) * sizeof(float); // 136 KB
    cudaFuncSetAttribute(main_kernel, cudaFuncAttributeMaxDynamicSharedMemorySize, (int)shmem);

    init_kernel<<<1, 512>>>();
    prep_kernel<<<B_*N_, C1>>>(X, W1, b1);
    dim3 grid(N_/TI, N_/TJ, B_);
    main_kernel<<<grid, 256, shmem>>>(W2, b2, W3, b3);
    head_kernel<<<1, 256>>>(F1, bf1, F2, bf2, (float*)d_out);
}

// round 5
// speedup vs baseline: 2.3607x; 2.3607x over previous
#include <cuda_runtime.h>
#include <cuda_bf16.h>
#include <cfloat>
#include <cstdint>

// PointPairNet: B=4, N=512, D=3
#define B_   4
#define N_   512
#define D_   3
#define C1   64
#define C3   128
#define TI   16
#define TJ   16
#define TP   256                        // pairs per tile
#define NTILES (B_*(N_/TI)*(N_/TJ))     // 4096
#define GRID_MAIN 592

// row pitch for bf16 matrices: 64 ch * 2B = 128B + 16B pad = 144B (conflict-free ldmatrix)
#define PITCH 144

// ---- smem offsets (bytes) ----
#define OFF_HH   0                      // H / H2 hi   256 x 144
#define OFF_HL   36864                  // H / H2 lo
#define OFF_W2H  73728                  // 64 x 144
#define OFF_W2L  82944
#define OFF_W3H  92160                  // 128 x 144
#define OFF_W3L  110592
#define OFF_U    129024                 // 16 x 64 f32
#define OFF_V    133120                 // 16 x 64 f32
#define OFF_B2   137216                 // 64 f32
#define OFF_B3   137472                 // 128 f32
#define SMEM_TOTAL 137984
#define WIMG_BYTES 55296                // W2h(9216)+W2l(9216)+W3h(18432)+W3l(18432)

__device__ __align__(16) unsigned char g_Wimg[WIMG_BYTES];
__device__ float    g_U[B_*N_*C1];
__device__ float    g_V[B_*N_*C1];
__device__ unsigned g_Penc[B_*C3];

// ---------------- helpers ----------------
__device__ __forceinline__ uint32_t smem_u32(const void* p) {
    uint32_t a;
    asm("{ .reg .u64 t; cvta.to.shared.u64 t, %1; cvt.u32.u64 %0, t; }" : "=r"(a) : "l"(p));
    return a;
}
__device__ __forceinline__ void ldmx4(uint32_t r[4], uint32_t addr) {
    asm volatile("ldmatrix.sync.aligned.m8n8.x4.shared.b16 {%0,%1,%2,%3}, [%4];"
        : "=r"(r[0]), "=r"(r[1]), "=r"(r[2]), "=r"(r[3]) : "r"(addr));
}
__device__ __forceinline__ void mma16816(float c[4], const uint32_t a[4],
                                         uint32_t b0, uint32_t b1) {
    asm volatile("mma.sync.aligned.m16n8k16.row.col.f32.bf16.bf16.f32 "
        "{%0,%1,%2,%3}, {%4,%5,%6,%7}, {%8,%9}, {%0,%1,%2,%3};"
        : "+f"(c[0]), "+f"(c[1]), "+f"(c[2]), "+f"(c[3])
        : "r"(a[0]), "r"(a[1]), "r"(a[2]), "r"(a[3]), "r"(b0), "r"(b1));
}
// A-fragment ldmatrix address (m16k16, row-major, pitch 144B)
__device__ __forceinline__ uint32_t addrA(uint32_t base, int prow, int kt, int lane) {
    return base + (uint32_t)((prow + (lane & 15)) * PITCH + kt * 32 + ((lane >> 4) << 4));
}
// B-fragment pair address (two n8k16 frags: rows c0..c0+15 of weight matrix)
__device__ __forceinline__ uint32_t addrB(uint32_t base, int c0, int kt, int lane) {
    int row = c0 + (lane & 7) + (((lane >> 4) & 1) << 3);
    int col = kt * 32 + (((lane >> 3) & 1) << 4);
    return base + (uint32_t)(row * PITCH + col);
}
// bf16 hi/lo split of two floats packed into bf16x2 words
__device__ __forceinline__ void split_pack(float a, float b, uint32_t& hi, uint32_t& lo) {
    __nv_bfloat16 ah = __float2bfloat16(a), bh = __float2bfloat16(b);
    float ar = a - __bfloat162float(ah), br = b - __bfloat162float(bh);
    __nv_bfloat16 al = __float2bfloat16(ar), bl = __float2bfloat16(br);
    hi = ((uint32_t)__bfloat16_as_ushort(bh) << 16) | (uint32_t)__bfloat16_as_ushort(ah);
    lo = ((uint32_t)__bfloat16_as_ushort(bl) << 16) | (uint32_t)__bfloat16_as_ushort(al);
}
__device__ __forceinline__ unsigned encf(float f) {
    unsigned u = __float_as_uint(f);
    return (u & 0x80000000u) ? ~u : (u | 0x80000000u);
}
__device__ __forceinline__ float decf(unsigned e) {
    return __uint_as_float((e & 0x80000000u) ? (e & 0x7FFFFFFFu) : ~e);
}

// ---------------- prep: first linear split ----------------
__global__ void prep_kernel(const float* __restrict__ X, const float* __restrict__ W1,
                            const float* __restrict__ b1) {
    int row = blockIdx.x;
    int c   = threadIdx.x;
    const float* x = X + row * D_;
    float x0 = x[0], x1 = x[1], x2 = x[2];
    const float* w = W1 + c * (2*D_);
    g_V[row*C1 + c] = x0*w[0] + x1*w[1] + x2*w[2];
    g_U[row*C1 + c] = x0*w[3] + x1*w[4] + x2*w[5] + b1[c];
}

// ---------------- prep: weight split into padded global image; zero g_Penc ----------------
__global__ void prep_w_kernel(const float* __restrict__ W2, const float* __restrict__ W3) {
    int tid = blockIdx.x * blockDim.x + threadIdx.x;   // 12288
    if (tid < B_*C3) g_Penc[tid] = 0u;
    float w; uint32_t offh, offl;
    if (tid < 4096) {              // W2: 64x64
        int r = tid >> 6, k = tid & 63;
        w = W2[tid];
        offh = (uint32_t)(r*PITCH + k*2);
        offl = offh + 9216u;
    } else if (tid < 12288) {      // W3: 128x64
        int i = tid - 4096;
        int r = i >> 6, k = i & 63;
        w = W3[i];
        offh = 18432u + (uint32_t)(r*PITCH + k*2);
        offl = offh + 18432u;
    } else return;
    __nv_bfloat16 h = __float2bfloat16(w);
    __nv_bfloat16 l = __float2bfloat16(w - __bfloat162float(h));
    *(unsigned short*)(g_Wimg + offh) = __bfloat16_as_ushort(h);
    *(unsigned short*)(g_Wimg + offl) = __bfloat16_as_ushort(l);
}

// ---------------- main: HMMA per-pair MLP + max-pool ----------------
extern __shared__ unsigned char smem[];

__global__ void __launch_bounds__(256, 1)
main_kernel(const float* __restrict__ b2g, const float* __restrict__ b3g) {
    const uint32_t sb  = smem_u32(smem);
    const int tid  = threadIdx.x;
    const int lane = tid & 31;
    const int wrp  = tid >> 5;          // 0..7
    const int pr0  = wrp * 32;          // warp's pair-row base

    // ---- copy weight image + biases into smem ----
    for (int i = tid; i < WIMG_BYTES/16; i += 256)
        *(uint4*)(smem + OFF_W2H + i*16) = *(const uint4*)(g_Wimg + i*16);
    if (tid < C1)  ((float*)(smem + OFF_B2))[tid] = b2g[tid];
    if (tid < C3)  ((float*)(smem + OFF_B3))[tid] = b3g[tid];
    __syncthreads();

    // per-lane column biases for epilogue 2 (constant across tiles)
    const float* sB2 = (const float*)(smem + OFF_B2);
    const float* sB3 = (const float*)(smem + OFF_B3);
    float b2c0[8], b2c1[8];
    #pragma unroll
    for (int nt = 0; nt < 8; ++nt) {
        b2c0[nt] = sB2[nt*8 + 2*(lane & 3)];
        b2c1[nt] = sB2[nt*8 + 2*(lane & 3) + 1];
    }

    const uint32_t aHH = sb + OFF_HH, aHL = sb + OFF_HL;
    const uint32_t aW2H = sb + OFF_W2H, aW2L = sb + OFF_W2L;
    const uint32_t aW3H = sb + OFF_W3H, aW3L = sb + OFF_W3L;

    for (int t = blockIdx.x; t < NTILES; t += GRID_MAIN) {
        const int b  = t >> 10;
        const int rm = t & 1023;
        const int i0 = (rm >> 5) * TI;
        const int j0 = (rm & 31) * TJ;

        // ---- stage U/V tiles (16x64 f32 each) ----
        {
            const float4* Ug = (const float4*)(g_U + (b*N_ + i0)*C1);
            const float4* Vg = (const float4*)(g_V + (b*N_ + j0)*C1);
            ((float4*)(smem + OFF_U))[tid & 255] = Ug[tid];
            ((float4*)(smem + OFF_V))[tid & 255] = Vg[tid];
        }
        __syncthreads();

        // ---- phase 1: H[p][c] = relu(U[i][c] + V[j][c]); split -> hi/lo bf16 ----
        {
            const int p = tid;
            const int i = p >> 4, j = p & 15;
            const float4* ur = (const float4*)(smem + OFF_U + i*256);
            const float4* vr = (const float4*)(smem + OFF_V + j*256);
            #pragma unroll
            for (int cc = 0; cc < 8; ++cc) {
                float4 u0 = ur[2*cc], u1 = ur[2*cc+1];
                float4 v0 = vr[2*cc], v1 = vr[2*cc+1];
                float h[8];
                h[0]=fmaxf(u0.x+v0.x,0.f); h[1]=fmaxf(u0.y+v0.y,0.f);
                h[2]=fmaxf(u0.z+v0.z,0.f); h[3]=fmaxf(u0.w+v0.w,0.f);
                h[4]=fmaxf(u1.x+v1.x,0.f); h[5]=fmaxf(u1.y+v1.y,0.f);
                h[6]=fmaxf(u1.z+v1.z,0.f); h[7]=fmaxf(u1.w+v1.w,0.f);
                uint32_t hi[4], lo[4];
                #pragma unroll
                for (int q = 0; q < 4; ++q) split_pack(h[2*q], h[2*q+1], hi[q], lo[q]);
                *(uint4*)(smem + OFF_HH + p*PITCH + cc*16) = make_uint4(hi[0],hi[1],hi[2],hi[3]);
                *(uint4*)(smem + OFF_HL + p*PITCH + cc*16) = make_uint4(lo[0],lo[1],lo[2],lo[3]);
            }
        }
        __syncwarp();

        // ---- layer 2: D2[m32][n64] = H @ W2^T, 3-term bf16 split ----
        float c2[2][8][4];
        #pragma unroll
        for (int mt = 0; mt < 2; ++mt)
            #pragma unroll
            for (int nt = 0; nt < 8; ++nt)
                #pragma unroll
                for (int q = 0; q < 4; ++q) c2[mt][nt][q] = 0.f;

        #pragma unroll
        for (int kt = 0; kt < 4; ++kt) {
            uint32_t aH0[4], aH1[4], aL0[4], aL1[4];
            ldmx4(aH0, addrA(aHH, pr0,      kt, lane));
            ldmx4(aH1, addrA(aHH, pr0 + 16, kt, lane));
            ldmx4(aL0, addrA(aHL, pr0,      kt, lane));
            ldmx4(aL1, addrA(aHL, pr0 + 16, kt, lane));
            #pragma unroll
            for (int np = 0; np < 4; ++np) {    // n-tile pairs
                uint32_t bH[4], bL[4];
                ldmx4(bH, addrB(aW2H, np*16, kt, lane));
                ldmx4(bL, addrB(aW2L, np*16, kt, lane));
                #pragma unroll
                for (int h = 0; h < 2; ++h) {   // n-tile within pair
                    const int nt = np*2 + h;
                    mma16816(c2[0][nt], aH0, bH[2*h], bH[2*h+1]);
                    mma16816(c2[1][nt], aH1, bH[2*h], bH[2*h+1]);
                    mma16816(c2[0][nt], aH0, bL[2*h], bL[2*h+1]);
                    mma16816(c2[1][nt], aH1, bL[2*h], bL[2*h+1]);
                    mma16816(c2[0][nt], aL0, bH[2*h], bH[2*h+1]);
                    mma16816(c2[1][nt], aL1, bH[2*h], bH[2*h+1]);
                }
            }
        }

        // ---- epilogue 2: bias+relu+split -> H2 (same buffers, own rows only) ----
        {
            const int colb = 2*(lane & 3);
            #pragma unroll
            for (int mt = 0; mt < 2; ++mt) {
                #pragma unroll
                for (int hf = 0; hf < 2; ++hf) {
                    const int row = pr0 + mt*16 + (lane >> 2) + hf*8;
                    #pragma unroll
                    for (int nt = 0; nt < 8; ++nt) {
                        float v0 = fmaxf(c2[mt][nt][hf*2]   + b2c0[nt], 0.f);
                        float v1 = fmaxf(c2[mt][nt][hf*2+1] + b2c1[nt], 0.f);
                        uint32_t hi, lo;
                        split_pack(v0, v1, hi, lo);
                        const uint32_t off = (uint32_t)(row*PITCH + (nt*8 + colb)*2);
                        *(uint32_t*)(smem + OFF_HH + off) = hi;
                        *(uint32_t*)(smem + OFF_HL + off) = lo;
                    }
                }
            }
        }
        __syncwarp();

        // ---- layer 3: D3[m32][n128] = H2 @ W3^T; fold max over pairs ----
        uint32_t a3H[2][4][4], a3L[2][4][4];
        #pragma unroll
        for (int mt = 0; mt < 2; ++mt)
            #pragma unroll
            for (int kt = 0; kt < 4; ++kt) {
                ldmx4(a3H[mt][kt], addrA(aHH, pr0 + mt*16, kt, lane));
                ldmx4(a3L[mt][kt], addrA(aHL, pr0 + mt*16, kt, lane));
            }

        float rm0[16], rm1[16];
        #pragma unroll
        for (int g = 0; g < 16; ++g) { rm0[g] = -FLT_MAX; rm1[g] = -FLT_MAX; }

        #pragma unroll
        for (int np = 0; np < 8; ++np) {
            float c3[2][2][4];
            #pragma unroll
            for (int mt = 0; mt < 2; ++mt)
                #pragma unroll
                for (int h = 0; h < 2; ++h)
                    #pragma unroll
                    for (int q = 0; q < 4; ++q) c3[mt][h][q] = 0.f;
            #pragma unroll
            for (int kt = 0; kt < 4; ++kt) {
                uint32_t bH[4], bL[4];
                ldmx4(bH, addrB(aW3H, np*16, kt, lane));
                ldmx4(bL, addrB(aW3L, np*16, kt, lane));
                #pragma unroll
                for (int h = 0; h < 2; ++h) {
                    #pragma unroll
                    for (int mt = 0; mt < 2; ++mt) {
                        mma16816(c3[mt][h], a3H[mt][kt], bH[2*h], bH[2*h+1]);
                        mma16816(c3[mt][h], a3H[mt][kt], bL[2*h], bL[2*h+1]);
                        mma16816(c3[mt][h], a3L[mt][kt], bH[2*h], bH[2*h+1]);
                    }
                }
            }
            #pragma unroll
            for (int h = 0; h < 2; ++h) {
                const int g = np*2 + h;
                rm0[g] = fmaxf(rm0[g], fmaxf(fmaxf(c3[0][h][0], c3[0][h][2]),
                                             fmaxf(c3[1][h][0], c3[1][h][2])));
                rm1[g] = fmaxf(rm1[g], fmaxf(fmaxf(c3[0][h][1], c3[0][h][3]),
                                             fmaxf(c3[1][h][1], c3[1][h][3])));
            }
        }

        // cross-lane reduce (lanes sharing the same columns: xor 4, 8, 16)
        #pragma unroll
        for (int g = 0; g < 16; ++g) {
            float v0 = rm0[g], v1 = rm1[g];
            #pragma unroll
            for (int s = 4; s < 32; s <<= 1) {
                v0 = fmaxf(v0, __shfl_xor_sync(0xFFFFFFFFu, v0, s));
                v1 = fmaxf(v1, __shfl_xor_sync(0xFFFFFFFFu, v1, s));
            }
            rm0[g] = v0; rm1[g] = v1;
        }
        if (lane < 4) {
            #pragma unroll
            for (int g = 0; g < 16; ++g) {
                const int d0 = g*8 + 2*lane;
                atomicMax(&g_Penc[b*C3 + d0],     encf(rm0[g] + sB3[d0]));
                atomicMax(&g_Penc[b*C3 + d0 + 1], encf(rm1[g] + sB3[d0 + 1]));
            }
        }
        __syncthreads();
    }
}

// ---------------- head MLP ----------------
__global__ void head_kernel(const float* __restrict__ F1, const float* __restrict__ bf1,
                            const float* __restrict__ F2, const float* __restrict__ bf2,
                            float* __restrict__ out) {
    __shared__ float P[B_*C3];
    __shared__ float Z[B_*64];
    const int tid = threadIdx.x;   // 256
    for (int t = tid; t < B_*C3; t += 256) P[t] = decf(g_Penc[t]);
    __syncthreads();
    {
        const int b = tid >> 6, e = tid & 63;
        float acc = bf1[e];
        #pragma unroll 4
        for (int d = 0; d < C3; ++d) acc += P[b*C3 + d] * F1[e*C3 + d];
        Z[b*64 + e] = fmaxf(acc, 0.f);
    }
    __syncthreads();
    if (tid < B_*2) {
        const int b = tid >> 1, o = tid & 1;
        float acc = bf2[o];
        #pragma unroll 4
        for (int e = 0; e < 64; ++e) acc += Z[b*64 + e] * F2[o*64 + e];
        out[b*2 + o] = acc;
    }
}

// ---------------- launch ----------------
extern "C" void kernel_launch(void* const* d_in, const int* in_sizes, int n_in,
                              void* d_out, int out_size) {
    const float* X   = (const float*)d_in[0];
    const float* W1  = (const float*)d_in[1];
    const float* b1  = (const float*)d_in[2];
    const float* W2  = (const float*)d_in[3];
    const float* b2  = (const float*)d_in[4];
    const float* W3  = (const float*)d_in[5];
    const float* b3  = (const float*)d_in[6];
    const float* F1  = (const float*)d_in[7];
    const float* bf1 = (const float*)d_in[8];
    const float* F2  = (const float*)d_in[9];
    const float* bf2 = (const float*)d_in[10];

    cudaFuncSetAttribute(main_kernel, cudaFuncAttributeMaxDynamicSharedMemorySize, SMEM_TOTAL);

    prep_kernel<<<B_*N_, C1>>>(X, W1, b1);
    prep_w_kernel<<<96, 128>>>(W2, W3);
    main_kernel<<<GRID_MAIN, 256, SMEM_TOTAL>>>(b2, b3);
    head_kernel<<<1, 256>>>(F1, bf1, F2, bf2, (float*)d_out);
}

// round 9
// speedup vs baseline: 4.2241x; 1.7893x over previous
#include <cuda_runtime.h>
#include <cuda_bf16.h>
#include <cfloat>
#include <cstdint>

// PointPairNet: B=4, N=512, D=3
#define B_   4
#define N_   512
#define D_   3
#define C1   64
#define C3   128
#define TI   8
#define TJ   16
#define TP   128                        // pairs per tile
#define TILES_PER_B 2048                // (512/8)*(512/16)
#define BLK_PER_B   74
#define GRID_MAIN   296                 // 4 batches * 74 = 2 CTAs/SM * 148

#define PITCH  144                      // bf16 matrix row pitch (128+16)
#define UPITCH 272                      // U/V f32 row pitch (256+16)

// ---- smem offsets (bytes) ----
#define OFF_HH   0                      // H / H2 hi   128x144
#define OFF_HL   18432                  // H / H2 lo
#define OFF_W2H  36864                  // 64x144
#define OFF_W2L  46080
#define OFF_W3H  55296                  // 128x144
#define OFF_W3L  73728
#define OFF_U0   92160                  // 8 x UPITCH
#define OFF_U1   94336
#define OFF_V0   96512                  // 16 x UPITCH
#define OFF_V1   100864
#define OFF_B2   105216                 // 64 f32
#define OFF_B3   105472                 // 128 f32
#define SMEM_TOTAL 105984
#define WIMG_BYTES 55296                // W2h(9216)+W2l(9216)+W3h(18432)+W3l(18432)

__device__ __align__(16) unsigned char g_Wimg[WIMG_BYTES];
__device__ float    g_U[B_*N_*C1];
__device__ float    g_V[B_*N_*C1];
__device__ unsigned g_Penc[B_*C3];

// ---------------- helpers ----------------
__device__ __forceinline__ uint32_t smem_u32(const void* p) {
    uint32_t a;
    asm("{ .reg .u64 t; cvta.to.shared.u64 t, %1; cvt.u32.u64 %0, t; }" : "=r"(a) : "l"(p));
    return a;
}
__device__ __forceinline__ void ldmx4(uint32_t r[4], uint32_t addr) {
    asm volatile("ldmatrix.sync.aligned.m8n8.x4.shared.b16 {%0,%1,%2,%3}, [%4];"
        : "=r"(r[0]), "=r"(r[1]), "=r"(r[2]), "=r"(r[3]) : "r"(addr));
}
__device__ __forceinline__ void mma16816(float c[4], const uint32_t a[4],
                                         uint32_t b0, uint32_t b1) {
    asm volatile("mma.sync.aligned.m16n8k16.row.col.f32.bf16.bf16.f32 "
        "{%0,%1,%2,%3}, {%4,%5,%6,%7}, {%8,%9}, {%0,%1,%2,%3};"
        : "+f"(c[0]), "+f"(c[1]), "+f"(c[2]), "+f"(c[3])
        : "r"(a[0]), "r"(a[1]), "r"(a[2]), "r"(a[3]), "r"(b0), "r"(b1));
}
// A-fragment ldmatrix address (m16k16, row-major, pitch 144B)
__device__ __forceinline__ uint32_t addrA(uint32_t base, int prow, int kt, int lane) {
    return base + (uint32_t)((prow + (lane & 15)) * PITCH + kt * 32 + ((lane >> 4) << 4));
}
// B-fragment pair address (two n8k16 frags: rows c0..c0+15 of weight matrix)
__device__ __forceinline__ uint32_t addrB(uint32_t base, int c0, int kt, int lane) {
    int row = c0 + (lane & 7) + (((lane >> 4) & 1) << 3);
    int col = kt * 32 + (((lane >> 3) & 1) << 4);
    return base + (uint32_t)(row * PITCH + col);
}
__device__ __forceinline__ void split_pack(float a, float b, uint32_t& hi, uint32_t& lo) {
    __nv_bfloat16 ah = __float2bfloat16(a), bh = __float2bfloat16(b);
    float ar = a - __bfloat162float(ah), br = b - __bfloat162float(bh);
    __nv_bfloat16 al = __float2bfloat16(ar), bl = __float2bfloat16(br);
    hi = ((uint32_t)__bfloat16_as_ushort(bh) << 16) | (uint32_t)__bfloat16_as_ushort(ah);
    lo = ((uint32_t)__bfloat16_as_ushort(bl) << 16) | (uint32_t)__bfloat16_as_ushort(al);
}
__device__ __forceinline__ unsigned encf(float f) {
    unsigned u = __float_as_uint(f);
    return (u & 0x80000000u) ? ~u : (u | 0x80000000u);
}
__device__ __forceinline__ float decf(unsigned e) {
    return __uint_as_float((e & 0x80000000u) ? (e & 0x7FFFFFFFu) : ~e);
}

// ---------------- prep: first linear split ----------------
__global__ void prep_kernel(const float* __restrict__ X, const float* __restrict__ W1,
                            const float* __restrict__ b1) {
    int row = blockIdx.x;
    int c   = threadIdx.x;
    const float* x = X + row * D_;
    float x0 = x[0], x1 = x[1], x2 = x[2];
    const float* w = W1 + c * (2*D_);
    g_V[row*C1 + c] = x0*w[0] + x1*w[1] + x2*w[2];
    g_U[row*C1 + c] = x0*w[3] + x1*w[4] + x2*w[5] + b1[c];
}

// ---------------- prep: weight split into padded global image; zero g_Penc ----------------
__global__ void prep_w_kernel(const float* __restrict__ W2, const float* __restrict__ W3) {
    int tid = blockIdx.x * blockDim.x + threadIdx.x;   // 12288
    if (tid < B_*C3) g_Penc[tid] = 0u;
    float w; uint32_t offh, offl;
    if (tid < 4096) {              // W2: 64x64
        int r = tid >> 6, k = tid & 63;
        w = W2[tid];
        offh = (uint32_t)(r*PITCH + k*2);
        offl = offh + 9216u;
    } else if (tid < 12288) {      // W3: 128x64
        int i = tid - 4096;
        int r = i >> 6, k = i & 63;
        w = W3[i];
        offh = 18432u + (uint32_t)(r*PITCH + k*2);
        offl = offh + 18432u;
    } else return;
    __nv_bfloat16 h = __float2bfloat16(w);
    __nv_bfloat16 l = __float2bfloat16(w - __bfloat162float(h));
    *(unsigned short*)(g_Wimg + offh) = __bfloat16_as_ushort(h);
    *(unsigned short*)(g_Wimg + offl) = __bfloat16_as_ushort(l);
}

// ---------------- main: HMMA per-pair MLP + max-pool (2 CTA/SM) ----------------
extern __shared__ unsigned char smem[];

__global__ void __launch_bounds__(256, 2)
main_kernel(const float* __restrict__ b2g, const float* __restrict__ b3g) {
    const uint32_t sb  = smem_u32(smem);
    const int tid  = threadIdx.x;
    const int lane = tid & 31;
    const int wrp  = tid >> 5;          // 0..7
    const int pr0  = wrp * 16;          // warp's 16 pair-rows

    // ---- copy weight image + biases into smem ----
    for (int i = tid; i < WIMG_BYTES/16; i += 256)
        *(uint4*)(smem + OFF_W2H + i*16) = *(const uint4*)(g_Wimg + i*16);
    if (tid < C1)  ((float*)(smem + OFF_B2))[tid] = b2g[tid];
    if (tid < C3)  ((float*)(smem + OFF_B3))[tid] = b3g[tid];

    const float* sB2 = (const float*)(smem + OFF_B2);
    const float* sB3 = (const float*)(smem + OFF_B3);
    const uint32_t aHH = sb + OFF_HH, aHL = sb + OFF_HL;
    const uint32_t aW2H = sb + OFF_W2H, aW2L = sb + OFF_W2L;
    const uint32_t aW3H = sb + OFF_W3H, aW3L = sb + OFF_W3L;

    const int b = blockIdx.x / BLK_PER_B;       // fixed batch per block
    const int s = blockIdx.x % BLK_PER_B;

    // running per-channel max across all this block's tiles (one batch)
    float rm0[16], rm1[16];
    #pragma unroll
    for (int g = 0; g < 16; ++g) { rm0[g] = -FLT_MAX; rm1[g] = -FLT_MAX; }

    // staging: thread loads 1 float4 of V, threads<128 also 1 of U
    const int srow = tid >> 4, sq = tid & 15;
    const bool hasU = tid < 128;
    const int urow = (tid & 127) >> 4;

    // ---- stage first tile into buffer 0 ----
    {
        const int i0 = (s >> 5) * TI, j0 = (s & 31) * TJ;
        float4 pv = *(const float4*)(g_V + (b*N_ + j0 + srow)*C1 + sq*4);
        *(float4*)(smem + OFF_V0 + srow*UPITCH + sq*16) = pv;
        if (hasU) {
            float4 pu = *(const float4*)(g_U + (b*N_ + i0 + urow)*C1 + sq*4);
            *(float4*)(smem + OFF_U0 + urow*UPITCH + sq*16) = pu;
        }
    }

    int sel = 0;
    for (int t = s; t < TILES_PER_B; t += BLK_PER_B) {
        __syncthreads();   // staged U/V + (next iter) H-buffer reuse visible

        const uint32_t uB = sb + (sel ? OFF_U1 : OFF_U0);
        const uint32_t vB = sb + (sel ? OFF_V1 : OFF_V0);

        // ---- phase 1: H[p][c] = relu(U[i][c] + V[j][c]); split -> hi/lo bf16 ----
        {
            const int r  = lane & 15;       // j within tile -> pair row pr0+r
            const int hf = lane >> 4;       // channel half (32 ch)
            const uint32_t ua = uB + (uint32_t)(wrp*UPITCH + hf*128);
            const uint32_t va = vB + (uint32_t)(r*UPITCH + hf*128);
            const int p = pr0 + r;
            #pragma unroll
            for (int q = 0; q < 4; ++q) {
                float4 u0 = *(const float4*)(smem + (ua - sb) + q*32);
                float4 u1 = *(const float4*)(smem + (ua - sb) + q*32 + 16);
                float4 v0 = *(const float4*)(smem + (va - sb) + q*32);
                float4 v1 = *(const float4*)(smem + (va - sb) + q*32 + 16);
                float h[8];
                h[0]=fmaxf(u0.x+v0.x,0.f); h[1]=fmaxf(u0.y+v0.y,0.f);
                h[2]=fmaxf(u0.z+v0.z,0.f); h[3]=fmaxf(u0.w+v0.w,0.f);
                h[4]=fmaxf(u1.x+v1.x,0.f); h[5]=fmaxf(u1.y+v1.y,0.f);
                h[6]=fmaxf(u1.z+v1.z,0.f); h[7]=fmaxf(u1.w+v1.w,0.f);
                uint32_t hi[4], lo[4];
                #pragma unroll
                for (int k = 0; k < 4; ++k) split_pack(h[2*k], h[2*k+1], hi[k], lo[k]);
                const uint32_t off = (uint32_t)(p*PITCH + hf*64 + q*16);
                *(uint4*)(smem + OFF_HH + off) = make_uint4(hi[0],hi[1],hi[2],hi[3]);
                *(uint4*)(smem + OFF_HL + off) = make_uint4(lo[0],lo[1],lo[2],lo[3]);
            }
        }
        __syncwarp();

        // ---- early prefetch (LDG) of next tile's U/V ----
        const int nx = t + BLK_PER_B;
        const bool hasNext = nx < TILES_PER_B;
        float4 pv, pu;
        if (hasNext) {
            const int ni0 = (nx >> 5) * TI, nj0 = (nx & 31) * TJ;
            pv = *(const float4*)(g_V + (b*N_ + nj0 + srow)*C1 + sq*4);
            if (hasU) pu = *(const float4*)(g_U + (b*N_ + ni0 + urow)*C1 + sq*4);
        }

        // ---- layer 2: D2[m16][n64] = H @ W2^T (3-term bf16 split) ----
        float c2[8][4];
        #pragma unroll
        for (int nt = 0; nt < 8; ++nt)
            #pragma unroll
            for (int q = 0; q < 4; ++q) c2[nt][q] = 0.f;

        #pragma unroll
        for (int kt = 0; kt < 4; ++kt) {
            uint32_t aH[4], aL[4];
            ldmx4(aH, addrA(aHH, pr0, kt, lane));
            ldmx4(aL, addrA(aHL, pr0, kt, lane));
            #pragma unroll
            for (int np = 0; np < 4; ++np) {
                uint32_t bH[4], bL[4];
                ldmx4(bH, addrB(aW2H, np*16, kt, lane));
                ldmx4(bL, addrB(aW2L, np*16, kt, lane));
                #pragma unroll
                for (int h = 0; h < 2; ++h) {
                    const int nt = np*2 + h;
                    mma16816(c2[nt], aH, bH[2*h], bH[2*h+1]);
                    mma16816(c2[nt], aH, bL[2*h], bL[2*h+1]);
                    mma16816(c2[nt], aL, bH[2*h], bH[2*h+1]);
                }
            }
        }

        // ---- late store (STS) of prefetched U/V into other buffer ----
        if (hasNext) {
            *(float4*)(smem + (sel ? OFF_V0 : OFF_V1) + srow*UPITCH + sq*16) = pv;
            if (hasU)
                *(float4*)(smem + (sel ? OFF_U0 : OFF_U1) + urow*UPITCH + sq*16) = pu;
        }

        // ---- epilogue 2: bias+relu+split -> H2 (own rows only) ----
        {
            const int colb = 2*(lane & 3);
            #pragma unroll
            for (int hf = 0; hf < 2; ++hf) {
                const int row = pr0 + (lane >> 2) + hf*8;
                #pragma unroll
                for (int nt = 0; nt < 8; ++nt) {
                    const int c0 = nt*8 + colb;
                    float v0 = fmaxf(c2[nt][hf*2]   + sB2[c0],     0.f);
                    float v1 = fmaxf(c2[nt][hf*2+1] + sB2[c0 + 1], 0.f);
                    uint32_t hi, lo;
                    split_pack(v0, v1, hi, lo);
                    const uint32_t off = (uint32_t)(row*PITCH + c0*2);
                    *(uint32_t*)(smem + OFF_HH + off) = hi;
                    *(uint32_t*)(smem + OFF_HL + off) = lo;
                }
            }
        }
        __syncwarp();

        // ---- layer 3: D3[m16][n128] = H2 @ W3^T; fold running max ----
        uint32_t a3H[4][4], a3L[4][4];
        #pragma unroll
        for (int kt = 0; kt < 4; ++kt) {
            ldmx4(a3H[kt], addrA(aHH, pr0, kt, lane));
            ldmx4(a3L[kt], addrA(aHL, pr0, kt, lane));
        }

        #pragma unroll
        for (int np = 0; np < 8; ++np) {
            float c3[2][4];
            #pragma unroll
            for (int h = 0; h < 2; ++h)
                #pragma unroll
                for (int q = 0; q < 4; ++q) c3[h][q] = 0.f;
            #pragma unroll
            for (int kt = 0; kt < 4; ++kt) {
                uint32_t bH[4], bL[4];
                ldmx4(bH, addrB(aW3H, np*16, kt, lane));
                ldmx4(bL, addrB(aW3L, np*16, kt, lane));
                #pragma unroll
                for (int h = 0; h < 2; ++h) {
                    mma16816(c3[h], a3H[kt], bH[2*h], bH[2*h+1]);
                    mma16816(c3[h], a3H[kt], bL[2*h], bL[2*h+1]);
                    mma16816(c3[h], a3L[kt], bH[2*h], bH[2*h+1]);
                }
            }
            #pragma unroll
            for (int h = 0; h < 2; ++h) {
                const int g = np*2 + h;
                rm0[g] = fmaxf(rm0[g], fmaxf(c3[h][0], c3[h][2]));
                rm1[g] = fmaxf(rm1[g], fmaxf(c3[h][1], c3[h][3]));
            }
        }
        sel ^= 1;
    }

    // ---- once per block: cross-lane reduce + atomic flush ----
    #pragma unroll
    for (int g = 0; g < 16; ++g) {
        float v0 = rm0[g], v1 = rm1[g];
        #pragma unroll
        for (int sft = 4; sft < 32; sft <<= 1) {
            v0 = fmaxf(v0, __shfl_xor_sync(0xFFFFFFFFu, v0, sft));
            v1 = fmaxf(v1, __shfl_xor_sync(0xFFFFFFFFu, v1, sft));
        }
        rm0[g] = v0; rm1[g] = v1;
    }
    if (lane < 4) {
        #pragma unroll
        for (int g = 0; g < 16; ++g) {
            const int d0 = g*8 + 2*lane;
            atomicMax(&g_Penc[b*C3 + d0],     encf(rm0[g] + sB3[d0]));
            atomicMax(&g_Penc[b*C3 + d0 + 1], encf(rm1[g] + sB3[d0 + 1]));
        }
    }
}

// ---------------- head MLP (smem-staged, conflict-free) ----------------
__global__ void head_kernel(const float* __restrict__ F1, const float* __restrict__ bf1,
                            const float* __restrict__ F2, const float* __restrict__ bf2,
                            float* __restrict__ out) {
    __shared__ float sF1[64*129];
    __shared__ float P[B_*C3];
    __shared__ float Z[B_*64];
    const int tid = threadIdx.x;   // 256
    for (int i = tid; i < B_*C3; i += 256) P[i] = decf(g_Penc[i]);
    for (int i = tid; i < 64*128; i += 256)
        sF1[(i >> 7)*129 + (i & 127)] = F1[i];
    __syncthreads();
    {
        const int b = tid >> 6, e = tid & 63;
        const float* pf = &sF1[e*129];
        const float* pp = &P[b*C3];
        float a0 = 0.f, a1 = 0.f, a2 = 0.f, a3 = 0.f;
        #pragma unroll
        for (int d = 0; d < C3; d += 4) {
            a0 += pp[d]   * pf[d];
            a1 += pp[d+1] * pf[d+1];
            a2 += pp[d+2] * pf[d+2];
            a3 += pp[d+3] * pf[d+3];
        }
        Z[b*64 + e] = fmaxf((a0+a1) + (a2+a3) + bf1[e], 0.f);
    }
    __syncthreads();
    if (tid < B_*2) {
        const int b = tid >> 1, o = tid & 1;
        float acc = bf2[o];
        #pragma unroll 8
        for (int e = 0; e < 64; ++e) acc += Z[b*64 + e] * F2[o*64 + e];
        out[b*2 + o] = acc;
    }
}

// ---------------- launch ----------------
extern "C" void kernel_launch(void* const* d_in, const int* in_sizes, int n_in,
                              void* d_out, int out_size) {
    const float* X   = (const float*)d_in[0];
    const float* W1  = (const float*)d_in[1];
    const float* b1  = (const float*)d_in[2];
    const float* W2  = (const float*)d_in[3];
    const float* b2  = (const float*)d_in[4];
    const float* W3  = (const float*)d_in[5];
    const float* b3  = (const float*)d_in[6];
    const float* F1  = (const float*)d_in[7];
    const float* bf1 = (const float*)d_in[8];
    const float* F2  = (const float*)d_in[9];
    const float* bf2 = (const float*)d_in[10];

    cudaFuncSetAttribute(main_kernel, cudaFuncAttributeMaxDynamicSharedMemorySize, SMEM_TOTAL);

    prep_kernel<<<B_*N_, C1>>>(X, W1, b1);
    prep_w_kernel<<<96, 128>>>(W2, W3);
    main_kernel<<<GRID_MAIN, 256, SMEM_TOTAL>>>(b2, b3);
    head_kernel<<<1, 256>>>(F1, bf1, F2, bf2, (float*)d_out);
}